// round 10
// baseline (speedup 1.0000x reference)
#include <cuda_runtime.h>
#include <cuda_bf16.h>

// QuantumFeatureExtractor — closed-form, float4 loads, branchless swizzled
// smem remap, float4 stores. All global memory instructions lane-contiguous.
//
//   m0 = cos(t4)cos(t0)cos(a0) + 0.5*sin(t4)cos(t2)*(cos(a0+a2) - cos(a0-a2))
//   m1 = cos(a1 + t1)
//   m2 = 0.5*cos(t0)*(cos(a0-a2) + cos(a0+a2))
//   m3 = cos(a1 + t1) * cos(t3) * cos(a3)
//
// Thread k (262144 total): j4 = k&31, i = (k>>5)&63, b = k>>11.
// Loads x4[in], x4[in+32] (in = b*4096 + i*64 + j4) -> 2 LDG.128, lane-
// contiguous. Thread computes patches 2*j4, 2*j4+1; results staged in
// warp-local smem at slot((p&1)<<5 | p>>1) (+64B pad between halves) so the
// reload for output patches t and t+32 is branchless AND conflict-free,
// and both STG.128 are lane-contiguous.

__device__ __forceinline__ float4 qfe_patch(float a0, float a1, float a2, float a3,
                                            float A, float Bp, float Ch,
                                            float ct3, float t1) {
    const float c0 = __cosf(a0);
    const float cp = __cosf(a0 + a2);   // cos(a0+a2)
    const float cm = __cosf(a0 - a2);   // cos(a0-a2)
    const float m1 = __cosf(a1 + t1);
    const float c3 = __cosf(a3);
    const float m0 = fmaf(A, c0, Bp * (cp - cm));   // Bp = 0.5 sin t4 cos t2
    const float m2 = Ch * (cm + cp);                // Ch = 0.5 cos t0
    const float m3 = m1 * (ct3 * c3);
    return make_float4(m0, m1, m2, m3);
}

__global__ void __launch_bounds__(256) qfe_main(const float4* __restrict__ x4,
                                                const float* __restrict__ tp,
                                                float4* __restrict__ out4) {
    // Per-warp staging: 64 slots + 4-slot (64 B) pad between the halves.
    // Even patches p -> slot p>>1 (offsets 0..511), odd patches -> slot
    // 32+(p>>1) shifted by the pad (offsets 576..1087): LDS phases mix
    // banks 0-15 (even half) with banks 16-31 (odd half) -> conflict-free.
    __shared__ float4 sm[8][68];

    const int k  = blockIdx.x * 256 + threadIdx.x;   // 262144 threads
    const int j4 = k & 31;          // float4 column -> patches 2j4, 2j4+1
    const int i  = (k >> 5) & 63;   // patch row
    const int b  = k >> 11;         // batch

    const int in = b * 4096 + i * 64 + j4;
    // Both loads issued back-to-back, lane-contiguous (512 B/warp each).
    const float4 rA = x4[in];        // row 2i:   a0,a1 | a0',a1'
    const float4 rB = x4[in + 32];   // row 2i+1: a2,a3 | a2',a3'

    // Uniform circuit params — evaluated while the loads are in flight.
    const float t0 = tp[0], t1 = tp[1], t2 = tp[2], t3 = tp[3], t4 = tp[4];
    float st4, ct4;
    __sincosf(t4, &st4, &ct4);
    const float ct0 = __cosf(t0);
    const float ct2 = __cosf(t2);
    const float ct3 = __cosf(t3);
    const float A  = ct4 * ct0;
    const float Bp = 0.5f * (st4 * ct2);
    const float Ch = 0.5f * ct0;

    const float4 oa = qfe_patch(rA.x, rA.y, rB.x, rB.y, A, Bp, Ch, ct3, t1);
    const float4 ob = qfe_patch(rA.z, rA.w, rB.z, rB.w, A, Bp, Ch, ct3, t1);

    const int w = threadIdx.x >> 5;   // warp in block
    const int t = j4;                 // lane
    float4* const smw = &sm[w][0];

    // Store: patch 2t (even) -> slot t; patch 2t+1 (odd) -> slot 36+t (pad).
    smw[t]      = oa;                 // linear, conflict-free
    smw[36 + t] = ob;                 // linear, conflict-free
    __syncwarp();

    // Branchless reload: patch p lives at slot ((p&1) ? 36+(p>>1) : (p>>1)).
    const int lo = ((t & 1) * 36) + (t >> 1);   // slot of patch t
    const float4 o_lo = smw[lo];                // patch t
    const float4 o_hi = smw[lo + 16];           // patch t+32 (same parity)

    // out float4 index = b*4096 + i*64 + patch. Lane-contiguous STG.128 x2.
    const int obase = in - j4;        // = b*4096 + i*64
    out4[obase + t]      = o_lo;
    out4[obase + 32 + t] = o_hi;
}

extern "C" void kernel_launch(void* const* d_in, const int* in_sizes, int n_in,
                              void* d_out, int out_size) {
    const float* x  = (const float*)d_in[0];
    const float* tp = (const float*)d_in[1];
    if (n_in >= 2 && in_sizes[0] == 6) {   // defensive vs metadata ordering
        const float* s = x; x = tp; tp = s;
    }
    qfe_main<<<1024, 256>>>((const float4*)x, tp, (float4*)d_out);
}

// round 11
// speedup vs baseline: 1.0435x; 1.0435x over previous
#include <cuda_runtime.h>
#include <cuda_bf16.h>

// QuantumFeatureExtractor — closed-form, float4 loads, single 256-bit store
// per thread (sm_103a st.global.v8.f32). No shared-memory remap needed:
// lane t's two patches (2t, 2t+1) are 32 contiguous output bytes, so one
// STG.256 per lane gives a 1024 B contiguous warp store in one instruction.
//
//   m0 = cos(t4)cos(t0)cos(a0) + 0.5*sin(t4)cos(t2)*(cos(a0+a2) - cos(a0-a2))
//   m1 = cos(a1 + t1)
//   m2 = 0.5*cos(t0)*(cos(a0-a2) + cos(a0+a2))
//   m3 = cos(a1 + t1) * cos(t3) * cos(a3)
// (final Rz(t5) is a diagonal phase: no effect on probabilities)

__device__ __forceinline__ float4 qfe_patch(float a0, float a1, float a2, float a3,
                                            float A, float Bp, float Ch,
                                            float ct3, float t1) {
    const float c0 = __cosf(a0);
    const float cp = __cosf(a0 + a2);   // cos(a0+a2)
    const float cm = __cosf(a0 - a2);   // cos(a0-a2)
    const float m1 = __cosf(a1 + t1);
    const float c3 = __cosf(a3);
    const float m0 = fmaf(A, c0, Bp * (cp - cm));   // Bp = 0.5 sin t4 cos t2
    const float m2 = Ch * (cm + cp);                // Ch = 0.5 cos t0
    const float m3 = m1 * (ct3 * c3);
    return make_float4(m0, m1, m2, m3);
}

__global__ void __launch_bounds__(256) qfe_main(const float4* __restrict__ x4,
                                                const float* __restrict__ tp,
                                                float* __restrict__ out) {
    const int k  = blockIdx.x * 256 + threadIdx.x;   // 262144 threads
    const int j4 = k & 31;          // float4 column -> patches 2j4, 2j4+1
    const int i  = (k >> 5) & 63;   // patch row
    const int b  = k >> 11;         // batch

    const int in = b * 4096 + i * 64 + j4;
    // Both loads issued back-to-back, lane-contiguous (512 B/warp each).
    const float4 rA = x4[in];        // row 2i:   a0,a1 | a0',a1'
    const float4 rB = x4[in + 32];   // row 2i+1: a2,a3 | a2',a3'

    // Uniform circuit params — evaluated while the loads are in flight.
    const float t0 = tp[0], t1 = tp[1], t2 = tp[2], t3 = tp[3], t4 = tp[4];
    float st4, ct4;
    __sincosf(t4, &st4, &ct4);
    const float ct0 = __cosf(t0);
    const float ct2 = __cosf(t2);
    const float ct3 = __cosf(t3);
    const float A  = ct4 * ct0;
    const float Bp = 0.5f * (st4 * ct2);
    const float Ch = 0.5f * ct0;

    const float4 oa = qfe_patch(rA.x, rA.y, rB.x, rB.y, A, Bp, Ch, ct3, t1);
    const float4 ob = qfe_patch(rA.z, rA.w, rB.z, rB.w, A, Bp, Ch, ct3, t1);

    // Output float4 index of patch 2*j4 = b*4096 + i*64 + 2*j4 = in + j4
    // (even -> 32 B aligned). Lane t covers bytes [32t, 32t+32) of the
    // warp's contiguous 1024 B span: one STG.256 per lane.
    float* dst = out + (size_t)(in + j4) * 4;
    asm volatile(
        "st.global.v8.f32 [%0], {%1, %2, %3, %4, %5, %6, %7, %8};"
        :: "l"(dst),
           "f"(oa.x), "f"(oa.y), "f"(oa.z), "f"(oa.w),
           "f"(ob.x), "f"(ob.y), "f"(ob.z), "f"(ob.w)
        : "memory");
}

extern "C" void kernel_launch(void* const* d_in, const int* in_sizes, int n_in,
                              void* d_out, int out_size) {
    const float* x  = (const float*)d_in[0];
    const float* tp = (const float*)d_in[1];
    if (n_in >= 2 && in_sizes[0] == 6) {   // defensive vs metadata ordering
        const float* s = x; x = tp; tp = s;
    }
    qfe_main<<<1024, 256>>>((const float4*)x, tp, (float*)d_out);
}